// round 13
// baseline (speedup 1.0000x reference)
#include <cuda_runtime.h>
#include <cuda_bf16.h>
#include <cstdint>

#define MAX_NODES 100000
#define MAX_EDGES 1600000
#define FEAT 64
#define FEAT4 16
#define SCAN_CHUNK 256
#define MAX_SCAN_BLOCKS ((MAX_NODES + SCAN_CHUNK - 1) / SCAN_CHUNK)   // 391

// Scratch (device globals; no allocation allowed)
__device__ float4 g_accum4[(size_t)MAX_NODES * FEAT4];
__device__ int    g_count[MAX_NODES];
__device__ int    g_off[MAX_NODES + 1];
__device__ int    g_cursor[MAX_NODES];
__device__ int    g_sorted[MAX_EDGES];
__device__ int    g_bsums[MAX_SCAN_BLOCKS];

// ---------------------------------------------------------------------------
// Packed f32x2 helpers (sm_103a; PTX-only path, full fp32 precision).
// ---------------------------------------------------------------------------
__device__ __forceinline__ uint64_t pack2(float lo, float hi) {
    uint64_t r;
    asm("mov.b64 %0, {%1, %2};" : "=l"(r) : "f"(lo), "f"(hi));
    return r;
}
__device__ __forceinline__ void unpack2(uint64_t v, float& lo, float& hi) {
    asm("mov.b64 {%0, %1}, %2;" : "=f"(lo), "=f"(hi) : "l"(v));
}
__device__ __forceinline__ void ffma2(uint64_t& d, uint64_t a, uint64_t b) {
    asm("fma.rn.f32x2 %0, %1, %2, %0;" : "+l"(d) : "l"(a), "l"(b));
}

// ---------------------------------------------------------------------------
// K0: zero degree counters.
// ---------------------------------------------------------------------------
__global__ void zero_count_kernel(int N) {
    int t = blockIdx.x * blockDim.x + threadIdx.x;
    if (t < N) g_count[t] = 0;
}

// ---------------------------------------------------------------------------
// K1: histogram of dst (degree counts).
// ---------------------------------------------------------------------------
__global__ void hist_kernel(const int* __restrict__ dst, int E) {
    int e = blockIdx.x * blockDim.x + threadIdx.x;
    if (e < E) atomicAdd(&g_count[dst[e]], 1);
}

// ---------------------------------------------------------------------------
// K2a: per-block reduction of counts -> block sums.
// ---------------------------------------------------------------------------
__global__ void scanA_kernel(int N) {
    __shared__ int warp_sums[8];
    int i = blockIdx.x * SCAN_CHUNK + threadIdx.x;
    int v = (i < N) ? g_count[i] : 0;
    for (int o = 16; o > 0; o >>= 1) v += __shfl_down_sync(0xffffffffu, v, o);
    if ((threadIdx.x & 31) == 0) warp_sums[threadIdx.x >> 5] = v;
    __syncthreads();
    if (threadIdx.x < 8) {
        int s = warp_sums[threadIdx.x];
        for (int o = 4; o > 0; o >>= 1) s += __shfl_down_sync(0xffu, s, o);
        if (threadIdx.x == 0) g_bsums[blockIdx.x] = s;
    }
}

// ---------------------------------------------------------------------------
// K2b (fused): each block derives its base from g_bsums[0..bid), then local
// exclusive scan -> offsets + cursor copy.
// ---------------------------------------------------------------------------
__global__ void scanC_kernel(int N) {
    __shared__ int s[SCAN_CHUNK];
    __shared__ int sbase;
    int t = threadIdx.x;

    int partial = 0;
    for (int b = t; b < (int)blockIdx.x; b += SCAN_CHUNK) partial += g_bsums[b];
    for (int o = 16; o > 0; o >>= 1)
        partial += __shfl_down_sync(0xffffffffu, partial, o);
    if ((t & 31) == 0) s[t >> 5] = partial;
    __syncthreads();
    if (t == 0) {
        int acc = 0;
        for (int w = 0; w < SCAN_CHUNK / 32; w++) acc += s[w];
        sbase = acc;
    }
    __syncthreads();
    int base = sbase;
    __syncthreads();

    int i = blockIdx.x * SCAN_CHUNK + t;
    int v = (i < N) ? g_count[i] : 0;
    s[t] = v;
    __syncthreads();
    for (int o = 1; o < SCAN_CHUNK; o <<= 1) {
        int x = (t >= o) ? s[t - o] : 0;
        __syncthreads();
        s[t] += x;
        __syncthreads();
    }
    int incl = s[t];
    if (i < N) {
        int off = base + incl - v;
        g_off[i] = off;
        g_cursor[i] = off;
        if (i == N - 1) g_off[N] = base + incl;
    }
}

// ---------------------------------------------------------------------------
// K3: reorder src into dst-sorted order.
// ---------------------------------------------------------------------------
__global__ void reorder_kernel(const int* __restrict__ src,
                               const int* __restrict__ dst, int E) {
    int e = blockIdx.x * blockDim.x + threadIdx.x;
    if (e < E) {
        int d = dst[e];
        int p = atomicAdd(&g_cursor[d], 1);
        g_sorted[p] = src[e];
    }
}

// ---------------------------------------------------------------------------
// K4: warp-per-node segmented gather-mean.
// Half-warps walk even/odd edges (2x unrolled => 4 loads in flight per lane);
// 16 lanes of each half own one float4 chunk of the 64-float row.
// shfl_xor(16) combines halves; mean divide fused here.
// ---------------------------------------------------------------------------
__global__ void gather_kernel(const float4* __restrict__ h4, int N) {
    int node = (blockIdx.x * blockDim.x + threadIdx.x) >> 5;
    if (node >= N) return;
    int lane = threadIdx.x & 31;
    int half = lane >> 4;
    int c    = lane & 15;

    int beg = g_off[node];
    int end = g_off[node + 1];

    float4 acc = make_float4(0.f, 0.f, 0.f, 0.f);
    int j = beg + half;
    for (; j + 2 < end; j += 4) {
        int s0 = g_sorted[j];
        int s1 = g_sorted[j + 2];
        float4 v0 = __ldg(h4 + (size_t)s0 * FEAT4 + c);
        float4 v1 = __ldg(h4 + (size_t)s1 * FEAT4 + c);
        acc.x += v0.x + v1.x; acc.y += v0.y + v1.y;
        acc.z += v0.z + v1.z; acc.w += v0.w + v1.w;
    }
    if (j < end) {
        int s0 = g_sorted[j];
        float4 v0 = __ldg(h4 + (size_t)s0 * FEAT4 + c);
        acc.x += v0.x; acc.y += v0.y; acc.z += v0.z; acc.w += v0.w;
    }

    acc.x += __shfl_xor_sync(0xffffffffu, acc.x, 16);
    acc.y += __shfl_xor_sync(0xffffffffu, acc.y, 16);
    acc.z += __shfl_xor_sync(0xffffffffu, acc.z, 16);
    acc.w += __shfl_xor_sync(0xffffffffu, acc.w, 16);

    if (half == 0) {
        float inv = 1.0f / fmaxf((float)(end - beg), 1.0f);
        acc.x *= inv; acc.y *= inv; acc.z *= inv; acc.w *= inv;
        g_accum4[(size_t)node * FEAT4 + c] = acc;   // stored as MEAN
    }
}

// ---------------------------------------------------------------------------
// K5: combine + linear with packed f32x2 FMA, row-major smem.
// Block = 256 threads -> 64 nodes x 64 outputs, 4x4 micro-tile per thread.
// sX[n][132], sW[o][132]: pad 132 => float4 staging STS conflict-free;
// phase 2 reads k-chunks of 4 via LDS.128 (rows are k-contiguous).
// ---------------------------------------------------------------------------
#define PAD 132
#define GEMM_SMEM_BYTES (2 * 64 * PAD * 4)   // 67584

__global__ void __launch_bounds__(256, 2)
fused_gemm_kernel(const float4* __restrict__ h4,
                  const float* __restrict__ W,
                  const float* __restrict__ b,
                  float* __restrict__ out,
                  int N) {
    extern __shared__ float smem[];
    float* sW = smem;                // [64][132]
    float* sX = smem + 64 * PAD;     // [64][132]

    const int tid = threadIdx.x;
    const int nb = blockIdx.x * 64;

    // Stage W: 64 rows x 32 quads. Coalesced LDG.128, lane-consecutive STS.128.
    for (int q = tid; q < 2048; q += 256) {
        int o  = q >> 5;
        int kq = q & 31;
        float4 v = *(const float4*)(W + o * 128 + kq * 4);
        *(float4*)(sW + o * PAD + kq * 4) = v;
    }

    // Stage X: 64 nodes x 32 quads (k<64 from h, k>=64 from gathered mean).
    for (int q = tid; q < 2048; q += 256) {
        int n  = q >> 5;
        int kq = q & 31;
        int gn = nb + n;
        float4 v = make_float4(0.f, 0.f, 0.f, 0.f);
        if (gn < N) {
            if (kq < 16) v = __ldg(h4 + (size_t)gn * FEAT4 + kq);
            else         v = g_accum4[(size_t)gn * FEAT4 + (kq - 16)];
        }
        *(float4*)(sX + n * PAD + kq * 4) = v;
    }
    __syncthreads();

    const int tx = tid & 15;   // output quad
    const int ty = tid >> 4;   // node quad

    uint64_t acc2[4][2];       // [node i][pair p]: outputs (4tx+2p, 4tx+2p+1)
    {
        uint64_t b01 = pack2(b[tx * 4 + 0], b[tx * 4 + 1]);
        uint64_t b23 = pack2(b[tx * 4 + 2], b[tx * 4 + 3]);
#pragma unroll
        for (int i = 0; i < 4; i++) { acc2[i][0] = b01; acc2[i][1] = b23; }
    }

#pragma unroll 4
    for (int kc = 0; kc < 128; kc += 4) {
        float4 xq[4], wq[4];
#pragma unroll
        for (int i = 0; i < 4; i++)
            xq[i] = *(const float4*)(sX + (ty * 4 + i) * PAD + kc);
#pragma unroll
        for (int j = 0; j < 4; j++)
            wq[j] = *(const float4*)(sW + (tx * 4 + j) * PAD + kc);

        // k = kc+0 .. kc+3; w pairs across j for each k; x duplicated pairs.
#pragma unroll
        for (int kk = 0; kk < 4; kk++) {
            float w0 = (&wq[0].x)[kk];
            float w1 = (&wq[1].x)[kk];
            float w2 = (&wq[2].x)[kk];
            float w3 = (&wq[3].x)[kk];
            uint64_t w01 = pack2(w0, w1);
            uint64_t w23 = pack2(w2, w3);
#pragma unroll
            for (int i = 0; i < 4; i++) {
                float xi = (&xq[i].x)[kk];
                uint64_t xx = pack2(xi, xi);
                ffma2(acc2[i][0], xx, w01);
                ffma2(acc2[i][1], xx, w23);
            }
        }
    }

#pragma unroll
    for (int i = 0; i < 4; i++) {
        int gn = nb + ty * 4 + i;
        if (gn < N) {
            float4 r;
            unpack2(acc2[i][0], r.x, r.y);
            unpack2(acc2[i][1], r.z, r.w);
            *(float4*)(out + (size_t)gn * 64 + tx * 4) = r;
        }
    }
}

// ---------------------------------------------------------------------------
// Launch
// ---------------------------------------------------------------------------
extern "C" void kernel_launch(void* const* d_in, const int* in_sizes, int n_in,
                              void* d_out, int out_size) {
    const float* h   = (const float*)d_in[0];
    const int*   src = (const int*)d_in[1];   // int32 indices
    const int*   dst = (const int*)d_in[2];
    const float* W   = (const float*)d_in[3];
    const float* b   = (const float*)d_in[4];
    float*       out = (float*)d_out;

    const int N = in_sizes[0] / FEAT;   // 100000
    const int E = in_sizes[1];          // 1600000
    const int NB = (N + SCAN_CHUNK - 1) / SCAN_CHUNK;   // 391

    zero_count_kernel<<<(N + 255) / 256, 256>>>(N);
    hist_kernel<<<(E + 255) / 256, 256>>>(dst, E);
    scanA_kernel<<<NB, SCAN_CHUNK>>>(N);
    scanC_kernel<<<NB, SCAN_CHUNK>>>(N);
    reorder_kernel<<<(E + 255) / 256, 256>>>(src, dst, E);
    gather_kernel<<<(N * 32 + 255) / 256, 256>>>((const float4*)h, N);

    cudaFuncSetAttribute(fused_gemm_kernel,
                         cudaFuncAttributeMaxDynamicSharedMemorySize,
                         GEMM_SMEM_BYTES);
    fused_gemm_kernel<<<(N + 63) / 64, 256, GEMM_SMEM_BYTES>>>(
        (const float4*)h, W, b, out, N);
}

// round 16
// speedup vs baseline: 1.2734x; 1.2734x over previous
#include <cuda_runtime.h>
#include <cuda_bf16.h>
#include <cstdint>

#define MAX_NODES 100000
#define MAX_EDGES 1600000
#define FEAT 64
#define FEAT4 16
#define SCAN_CHUNK 256
#define MAX_SCAN_BLOCKS ((MAX_NODES + SCAN_CHUNK - 1) / SCAN_CHUNK)   // 391

// W-pair layout: row k holds 32 u64 pairs (o=2p,2p+1), padded to 34 u64.
#define WP_ROW 34
// X-dup layout: row n holds 128 u64 dups (one per k), padded to 130 u64.
#define XD_ROW 130

// Scratch (device globals; no allocation allowed)
__device__ float4   g_accum4[(size_t)MAX_NODES * FEAT4];
__device__ int      g_count[MAX_NODES];
__device__ int      g_off[MAX_NODES + 1];
__device__ int      g_cursor[MAX_NODES];
__device__ int      g_sorted[MAX_EDGES];
__device__ int      g_bsums[MAX_SCAN_BLOCKS];
__device__ uint64_t g_Wp[128 * WP_ROW];          // pre-paired W, k-major

// ---------------------------------------------------------------------------
// Packed f32x2 helpers (sm_103a; PTX-only path, full fp32 precision).
// ---------------------------------------------------------------------------
__device__ __forceinline__ uint64_t pack2(float lo, float hi) {
    uint64_t r;
    asm("mov.b64 %0, {%1, %2};" : "=l"(r) : "f"(lo), "f"(hi));
    return r;
}
__device__ __forceinline__ void unpack2(uint64_t v, float& lo, float& hi) {
    asm("mov.b64 {%0, %1}, %2;" : "=f"(lo), "=f"(hi) : "l"(v));
}
__device__ __forceinline__ void ffma2(uint64_t& d, uint64_t a, uint64_t b) {
    asm("fma.rn.f32x2 %0, %1, %2, %0;" : "+l"(d) : "l"(a), "l"(b));
}

// ---------------------------------------------------------------------------
// K0: zero degree counters.
// ---------------------------------------------------------------------------
__global__ void zero_count_kernel(int N) {
    int t = blockIdx.x * blockDim.x + threadIdx.x;
    if (t < N) g_count[t] = 0;
}

// ---------------------------------------------------------------------------
// K0b: pre-pair W into k-major output-pair layout (runs once, tiny).
// g_Wp[k*WP_ROW + p] = (W[2p][k], W[2p+1][k])
// ---------------------------------------------------------------------------
__global__ void prep_w_kernel(const float* __restrict__ W) {
    int t = blockIdx.x * blockDim.x + threadIdx.x;   // 4096 threads
    if (t >= 128 * 32) return;
    int k = t >> 5;
    int p = t & 31;
    float w0 = W[(2 * p) * 128 + k];
    float w1 = W[(2 * p + 1) * 128 + k];
    g_Wp[k * WP_ROW + p] = pack2(w0, w1);
}

// ---------------------------------------------------------------------------
// K1: histogram of dst (degree counts).
// ---------------------------------------------------------------------------
__global__ void hist_kernel(const int* __restrict__ dst, int E) {
    int e = blockIdx.x * blockDim.x + threadIdx.x;
    if (e < E) atomicAdd(&g_count[dst[e]], 1);
}

// ---------------------------------------------------------------------------
// K2a: per-block reduction of counts -> block sums.
// ---------------------------------------------------------------------------
__global__ void scanA_kernel(int N) {
    __shared__ int warp_sums[8];
    int i = blockIdx.x * SCAN_CHUNK + threadIdx.x;
    int v = (i < N) ? g_count[i] : 0;
    for (int o = 16; o > 0; o >>= 1) v += __shfl_down_sync(0xffffffffu, v, o);
    if ((threadIdx.x & 31) == 0) warp_sums[threadIdx.x >> 5] = v;
    __syncthreads();
    if (threadIdx.x < 8) {
        int s = warp_sums[threadIdx.x];
        for (int o = 4; o > 0; o >>= 1) s += __shfl_down_sync(0xffu, s, o);
        if (threadIdx.x == 0) g_bsums[blockIdx.x] = s;
    }
}

// ---------------------------------------------------------------------------
// K2b (fused): each block derives its base from g_bsums[0..bid), then local
// exclusive scan -> offsets + cursor copy.
// ---------------------------------------------------------------------------
__global__ void scanC_kernel(int N) {
    __shared__ int s[SCAN_CHUNK];
    __shared__ int sbase;
    int t = threadIdx.x;

    int partial = 0;
    for (int b = t; b < (int)blockIdx.x; b += SCAN_CHUNK) partial += g_bsums[b];
    for (int o = 16; o > 0; o >>= 1)
        partial += __shfl_down_sync(0xffffffffu, partial, o);
    if ((t & 31) == 0) s[t >> 5] = partial;
    __syncthreads();
    if (t == 0) {
        int acc = 0;
        for (int w = 0; w < SCAN_CHUNK / 32; w++) acc += s[w];
        sbase = acc;
    }
    __syncthreads();
    int base = sbase;
    __syncthreads();

    int i = blockIdx.x * SCAN_CHUNK + t;
    int v = (i < N) ? g_count[i] : 0;
    s[t] = v;
    __syncthreads();
    for (int o = 1; o < SCAN_CHUNK; o <<= 1) {
        int x = (t >= o) ? s[t - o] : 0;
        __syncthreads();
        s[t] += x;
        __syncthreads();
    }
    int incl = s[t];
    if (i < N) {
        int off = base + incl - v;
        g_off[i] = off;
        g_cursor[i] = off;
        if (i == N - 1) g_off[N] = base + incl;
    }
}

// ---------------------------------------------------------------------------
// K3: reorder src into dst-sorted order.
// ---------------------------------------------------------------------------
__global__ void reorder_kernel(const int* __restrict__ src,
                               const int* __restrict__ dst, int E) {
    int e = blockIdx.x * blockDim.x + threadIdx.x;
    if (e < E) {
        int d = dst[e];
        int p = atomicAdd(&g_cursor[d], 1);
        g_sorted[p] = src[e];
    }
}

// ---------------------------------------------------------------------------
// K4: segmented gather-sum (R6-proven). 16 lanes per node; each lane owns one
// float4 of the row; 2x unrolled edge loop. Stores RAW sum.
// ---------------------------------------------------------------------------
__global__ void gather_kernel(const float4* __restrict__ h4, int N) {
    int idx = blockIdx.x * blockDim.x + threadIdx.x;
    int node = idx >> 4;
    int lane = idx & 15;
    if (node >= N) return;
    int beg = g_off[node];
    int end = g_off[node + 1];
    float4 acc = make_float4(0.f, 0.f, 0.f, 0.f);
    int j = beg;
    for (; j + 1 < end; j += 2) {
        int s0 = g_sorted[j];
        int s1 = g_sorted[j + 1];
        float4 v0 = __ldg(h4 + (size_t)s0 * FEAT4 + lane);
        float4 v1 = __ldg(h4 + (size_t)s1 * FEAT4 + lane);
        acc.x += v0.x; acc.y += v0.y; acc.z += v0.z; acc.w += v0.w;
        acc.x += v1.x; acc.y += v1.y; acc.z += v1.z; acc.w += v1.w;
    }
    if (j < end) {
        int s0 = g_sorted[j];
        float4 v0 = __ldg(h4 + (size_t)s0 * FEAT4 + lane);
        acc.x += v0.x; acc.y += v0.y; acc.z += v0.z; acc.w += v0.w;
    }
    g_accum4[(size_t)node * FEAT4 + lane] = acc;   // raw sum; divide in GEMM
}

// ---------------------------------------------------------------------------
// K5: combine + linear, f32x2 with ALL packing hoisted to staging.
// Block = 256 threads -> 64 nodes x 64 outputs, 4x4 micro-tile per thread.
//
// smem:
//   sWp: [128 k][WP_ROW u64]  w pairs (o=2p,2p+1), copied verbatim from g_Wp.
//        Read: LDS.128 at (k*34 + tx*2)*8 — tx*16B consecutive => conflict-free.
//   sXd: [64 n][XD_ROW u64]   x duplicated (x,x) per k.
//        Staged by the owning thread (consecutive STS) ; read broadcast.
//
// Inner loop per 2 k: 1 LDS.128 (w), 4 LDS.128 (x), 16 FFMA2, 0 MOVs.
// ---------------------------------------------------------------------------
#define GEMM_SMEM_BYTES ((128 * WP_ROW + 64 * XD_ROW) * 8)   // 101376

__global__ void __launch_bounds__(256, 2)
fused_gemm_kernel(const float4* __restrict__ h4,
                  const float* __restrict__ b,
                  float* __restrict__ out,
                  int N) {
    extern __shared__ uint64_t smem64[];
    uint64_t* sWp = smem64;                     // [128][34]
    uint64_t* sXd = smem64 + 128 * WP_ROW;      // [64][130]

    const int tid = threadIdx.x;
    const int nb = blockIdx.x * 64;

    // Stage W pairs: verbatim copy of g_Wp (4352 u64 = 2176 ulonglong2).
    for (int q = tid; q < 2176; q += 256) {
        *(ulonglong2*)(sWp + q * 2) = *(const ulonglong2*)(g_Wp + q * 2);
    }

    // Stage X duplicated: 64 nodes x 32 k-quads.
    for (int q = tid; q < 2048; q += 256) {
        int n  = q >> 5;
        int kq = q & 31;
        int gn = nb + n;
        float4 v = make_float4(0.f, 0.f, 0.f, 0.f);
        if (gn < N) {
            if (kq < 16) {
                v = __ldg(h4 + (size_t)gn * FEAT4 + kq);
            } else {
                v = g_accum4[(size_t)gn * FEAT4 + (kq - 16)];
                float inv = 1.0f / fmaxf((float)g_count[gn], 1.0f);
                v.x *= inv; v.y *= inv; v.z *= inv; v.w *= inv;
            }
        }
        uint64_t* p = sXd + n * XD_ROW + kq * 4;
        ulonglong2 d0, d1;
        d0.x = pack2(v.x, v.x); d0.y = pack2(v.y, v.y);
        d1.x = pack2(v.z, v.z); d1.y = pack2(v.w, v.w);
        *(ulonglong2*)(p)     = d0;
        *(ulonglong2*)(p + 2) = d1;
    }
    __syncthreads();

    const int tx = tid & 15;   // output quad (outs 4tx..4tx+3 = pairs 2tx,2tx+1)
    const int ty = tid >> 4;   // node quad  (nodes 4ty..4ty+3)

    uint64_t acc2[4][2];
    {
        uint64_t b01 = pack2(b[tx * 4 + 0], b[tx * 4 + 1]);
        uint64_t b23 = pack2(b[tx * 4 + 2], b[tx * 4 + 3]);
#pragma unroll
        for (int i = 0; i < 4; i++) { acc2[i][0] = b01; acc2[i][1] = b23; }
    }

    const uint64_t* wbase = sWp + tx * 2;
    const uint64_t* xbase = sXd + (ty * 4) * XD_ROW;

#pragma unroll 8
    for (int k = 0; k < 128; k += 2) {
        // w pairs for k and k+1
        ulonglong2 wA = *(const ulonglong2*)(wbase + k * WP_ROW);
        ulonglong2 wB = *(const ulonglong2*)(wbase + (k + 1) * WP_ROW);
        // x dups for nodes i=0..3, k and k+1 together (16B each)
        ulonglong2 x0 = *(const ulonglong2*)(xbase + 0 * XD_ROW + k);
        ulonglong2 x1 = *(const ulonglong2*)(xbase + 1 * XD_ROW + k);
        ulonglong2 x2 = *(const ulonglong2*)(xbase + 2 * XD_ROW + k);
        ulonglong2 x3 = *(const ulonglong2*)(xbase + 3 * XD_ROW + k);

        ffma2(acc2[0][0], x0.x, wA.x); ffma2(acc2[0][1], x0.x, wA.y);
        ffma2(acc2[1][0], x1.x, wA.x); ffma2(acc2[1][1], x1.x, wA.y);
        ffma2(acc2[2][0], x2.x, wA.x); ffma2(acc2[2][1], x2.x, wA.y);
        ffma2(acc2[3][0], x3.x, wA.x); ffma2(acc2[3][1], x3.x, wA.y);

        ffma2(acc2[0][0], x0.y, wB.x); ffma2(acc2[0][1], x0.y, wB.y);
        ffma2(acc2[1][0], x1.y, wB.x); ffma2(acc2[1][1], x1.y, wB.y);
        ffma2(acc2[2][0], x2.y, wB.x); ffma2(acc2[2][1], x2.y, wB.y);
        ffma2(acc2[3][0], x3.y, wB.x); ffma2(acc2[3][1], x3.y, wB.y);
    }

#pragma unroll
    for (int i = 0; i < 4; i++) {
        int gn = nb + ty * 4 + i;
        if (gn < N) {
            float4 r;
            unpack2(acc2[i][0], r.x, r.y);
            unpack2(acc2[i][1], r.z, r.w);
            *(float4*)(out + (size_t)gn * 64 + tx * 4) = r;
        }
    }
}

// ---------------------------------------------------------------------------
// Launch
// ---------------------------------------------------------------------------
extern "C" void kernel_launch(void* const* d_in, const int* in_sizes, int n_in,
                              void* d_out, int out_size) {
    const float* h   = (const float*)d_in[0];
    const int*   src = (const int*)d_in[1];   // int32 indices
    const int*   dst = (const int*)d_in[2];
    const float* W   = (const float*)d_in[3];
    const float* b   = (const float*)d_in[4];
    float*       out = (float*)d_out;

    const int N = in_sizes[0] / FEAT;   // 100000
    const int E = in_sizes[1];          // 1600000
    const int NB = (N + SCAN_CHUNK - 1) / SCAN_CHUNK;   // 391

    zero_count_kernel<<<(N + 255) / 256, 256>>>(N);
    prep_w_kernel<<<16, 256>>>(W);
    hist_kernel<<<(E + 255) / 256, 256>>>(dst, E);
    scanA_kernel<<<NB, SCAN_CHUNK>>>(N);
    scanC_kernel<<<NB, SCAN_CHUNK>>>(N);
    reorder_kernel<<<(E + 255) / 256, 256>>>(src, dst, E);
    gather_kernel<<<(N * 16 + 255) / 256, 256>>>((const float4*)h, N);

    cudaFuncSetAttribute(fused_gemm_kernel,
                         cudaFuncAttributeMaxDynamicSharedMemorySize,
                         GEMM_SMEM_BYTES);
    fused_gemm_kernel<<<(N + 63) / 64, 256, GEMM_SMEM_BYTES>>>(
        (const float4*)h, b, out, N);
}